// round 5
// baseline (speedup 1.0000x reference)
#include <cuda_runtime.h>
#include <math.h>

// Problem constants
#define NN 100000
#define EE 1600000
#define ET (EE + NN)      // edges + self loops
#define FF 128            // feature dim everywhere (IN = H*C = 128)
#define HH 4
#define CC 32
#define NEG_SLOPE 0.2f
#define SCAN_B 98         // 98 * 1024 >= NN

// ----------------------------------------------------------------------------
// Scratch (device globals; no allocations allowed)
// ----------------------------------------------------------------------------
__device__ float g_h[(size_t)NN * FF];     // transformed features of current layer
__device__ float g_feat[(size_t)NN * FF];  // input features for layers 1,2
__device__ __align__(16) float g_es[NN * HH];
__device__ __align__(16) float g_ed[NN * HH];
__device__ int   g_off[NN + 1];
__device__ int   g_cur[NN];                // counts, then cursors
__device__ int   g_csr[ET];                // src node per CSR slot (grouped by dst)
__device__ int   g_bsum[SCAN_B];
__device__ int   g_is64;                   // 1 if edge_index is int64, 0 if int32

// ----------------------------------------------------------------------------
// Packed f32x2 helpers (Blackwell: fma.rn.f32x2 doubles fp32 FMA throughput)
// ----------------------------------------------------------------------------
__device__ __forceinline__ unsigned long long pk(float lo, float hi) {
    unsigned long long r;
    asm("mov.b64 %0, {%1, %2};" : "=l"(r) : "f"(lo), "f"(hi));
    return r;
}
__device__ __forceinline__ void fma2(unsigned long long& d,
                                     unsigned long long a, unsigned long long b) {
    asm("fma.rn.f32x2 %0, %1, %2, %0;" : "+l"(d) : "l"(a), "l"(b));
}
__device__ __forceinline__ float2 unpk(unsigned long long v) {
    float lo, hi;
    asm("mov.b64 {%0, %1}, %2;" : "=f"(lo), "=f"(hi) : "l"(v));
    return make_float2(lo, hi);
}

// ----------------------------------------------------------------------------
// Edge index dtype probe (JAX may give int32 or int64)
// ----------------------------------------------------------------------------
__global__ void k_detect(const int* __restrict__ ei32) {
    if (threadIdx.x == 0) {
        int all0 = 1;
        for (int j = 1; j < 256; j += 2)
            if (ei32[j] != 0) { all0 = 0; break; }
        g_is64 = all0;
    }
}

__device__ __forceinline__ int load_edge(const void* ei, size_t idx) {
    if (g_is64) return (int)((const long long*)ei)[idx];
    return ((const int*)ei)[idx];
}

// ----------------------------------------------------------------------------
// CSR build: counting sort by dst
// ----------------------------------------------------------------------------
__global__ void k_init_counts() {
    int n = blockIdx.x * blockDim.x + threadIdx.x;
    if (n < NN) g_cur[n] = 1;  // self loop
}

__global__ void k_count(const void* __restrict__ ei) {
    int i = blockIdx.x * blockDim.x + threadIdx.x;
    if (i < EE) {
        int d = load_edge(ei, (size_t)EE + i);
        atomicAdd(&g_cur[d], 1);
    }
}

__global__ void __launch_bounds__(1024) k_blocksum() {
    __shared__ int sh[32];
    int t = threadIdx.x;
    int g = blockIdx.x * 1024 + t;
    int c = (g < NN) ? g_cur[g] : 0;
#pragma unroll
    for (int o = 16; o; o >>= 1) c += __shfl_xor_sync(0xffffffffu, c, o);
    if ((t & 31) == 0) sh[t >> 5] = c;
    __syncthreads();
    if (t < 32) {
        int v = sh[t];
#pragma unroll
        for (int o = 16; o; o >>= 1) v += __shfl_xor_sync(0xffffffffu, v, o);
        if (t == 0) g_bsum[blockIdx.x] = v;
    }
}

__global__ void k_scan_top() {
    __shared__ int sh[SCAN_B];
    int t = threadIdx.x;
    if (t < SCAN_B) sh[t] = g_bsum[t];
    __syncthreads();
    if (t == 0) {
        int run = 0;
        for (int i = 0; i < SCAN_B; i++) { int c = sh[i]; sh[i] = run; run += c; }
    }
    __syncthreads();
    if (t < SCAN_B) g_bsum[t] = sh[t];
}

__global__ void __launch_bounds__(1024) k_scan_final() {
    __shared__ int sh[1024];
    int t = threadIdx.x;
    int g = blockIdx.x * 1024 + t;
    int c = (g < NN) ? g_cur[g] : 0;
    sh[t] = c;
    __syncthreads();
#pragma unroll
    for (int off = 1; off < 1024; off <<= 1) {
        int v = (t >= off) ? sh[t - off] : 0;
        __syncthreads();
        sh[t] += v;
        __syncthreads();
    }
    int excl = sh[t] - c + g_bsum[blockIdx.x];
    if (g < NN) {
        g_off[g] = excl;
        g_cur[g] = excl;
    }
    if (g == 0) g_off[NN] = ET;
}

__global__ void k_scatter(const void* __restrict__ ei) {
    int i = blockIdx.x * blockDim.x + threadIdx.x;
    if (i >= ET) return;
    int s, d;
    if (i < EE) {
        s = load_edge(ei, i);
        d = load_edge(ei, (size_t)EE + i);
    } else {
        s = d = i - EE;  // self loop
    }
    int p = atomicAdd(&g_cur[d], 1);
    g_csr[p] = s;
}

// ----------------------------------------------------------------------------
// GEMM: g_h = X[N,128] @ W[128,128], fused attention-coefficient epilogue.
// 64-row tile, k-tiled by 32; 256 threads; thread owns 8 rows x 4 cols.
// Inner product uses packed fma.rn.f32x2 over k-pairs: accumulator holds
// (even-k partial, odd-k partial); halves summed in epilogue.
// ----------------------------------------------------------------------------
__global__ void __launch_bounds__(256) k_gemm(const float* __restrict__ Xext,
                                              const float* __restrict__ W,
                                              const float* __restrict__ a_src,
                                              const float* __restrict__ a_dst,
                                              int use_gfeat) {
    const float* X = use_gfeat ? g_feat : Xext;
    __shared__ __align__(16) float sX[64 * 32];
    __shared__ __align__(16) float sW[32 * 128];
    float4* sX4 = (float4*)sX;
    float4* sW4 = (float4*)sW;

    int tid = threadIdx.x;
    int row0 = blockIdx.x * 64;
    int cg = tid & 31;   // col group: cols 4*cg..4*cg+3 (also lane id)
    int rg = tid >> 5;   // row group (warp id): rows rg*8..rg*8+7

    unsigned long long acc2[8][4];
#pragma unroll
    for (int i = 0; i < 8; i++)
#pragma unroll
        for (int c = 0; c < 4; c++) acc2[i][c] = 0ULL;

    for (int kt = 0; kt < 4; kt++) {
        int k0 = kt * 32;
#pragma unroll
        for (int j = 0; j < 2; j++) {
            int idx = tid + 256 * j;
            int r = idx >> 3, c4 = idx & 7;
            float4 v = make_float4(0.f, 0.f, 0.f, 0.f);
            int gr = row0 + r;
            if (gr < NN) v = *(const float4*)(X + (size_t)gr * FF + k0 + 4 * c4);
            sX4[idx] = v;
        }
#pragma unroll
        for (int j = 0; j < 4; j++) {
            int idx = tid + 256 * j;
            int r = idx >> 5, c4 = idx & 31;
            sW4[idx] = *(const float4*)(W + (size_t)(k0 + r) * FF + 4 * c4);
        }
        __syncthreads();
#pragma unroll 4
        for (int kp = 0; kp < 16; kp++) {
            float4 w0 = sW4[(2 * kp) * 32 + cg];
            float4 w1 = sW4[(2 * kp + 1) * 32 + cg];
            unsigned long long b0 = pk(w0.x, w1.x);
            unsigned long long b1 = pk(w0.y, w1.y);
            unsigned long long b2 = pk(w0.z, w1.z);
            unsigned long long b3 = pk(w0.w, w1.w);
#pragma unroll
            for (int i = 0; i < 8; i++) {
                float2 xv = *(const float2*)(sX + (rg * 8 + i) * 32 + 2 * kp);
                unsigned long long a = pk(xv.x, xv.y);
                fma2(acc2[i][0], a, b0);
                fma2(acc2[i][1], a, b1);
                fma2(acc2[i][2], a, b2);
                fma2(acc2[i][3], a, b3);
            }
        }
        __syncthreads();
    }

    float4 asv = *(const float4*)(a_src + 4 * cg);
    float4 adv = *(const float4*)(a_dst + 4 * cg);
    int head = cg >> 3;

#pragma unroll
    for (int i = 0; i < 8; i++) {
        float2 u0 = unpk(acc2[i][0]);
        float2 u1 = unpk(acc2[i][1]);
        float2 u2 = unpk(acc2[i][2]);
        float2 u3 = unpk(acc2[i][3]);
        float a0 = u0.x + u0.y;
        float a1 = u1.x + u1.y;
        float a2 = u2.x + u2.y;
        float a3 = u3.x + u3.y;

        int gr = row0 + rg * 8 + i;
        float vs = a0 * asv.x + a1 * asv.y + a2 * asv.z + a3 * asv.w;
        float vd = a0 * adv.x + a1 * adv.y + a2 * adv.z + a3 * adv.w;
#pragma unroll
        for (int o = 4; o; o >>= 1) {
            vs += __shfl_xor_sync(0xffffffffu, vs, o);
            vd += __shfl_xor_sync(0xffffffffu, vd, o);
        }
        if (gr < NN) {
            *(float4*)(g_h + (size_t)gr * FF + 4 * cg) = make_float4(a0, a1, a2, a3);
            if ((cg & 7) == 0) {
                g_es[gr * HH + head] = vs;
                g_ed[gr * HH + head] = vd;
            }
        }
    }
}

// ----------------------------------------------------------------------------
// Edge phase: per dst node, max-free softmax over incoming edges + aggregation.
// One 128-thread block per node; thread t owns channel t (head t>>5).
// ----------------------------------------------------------------------------
__global__ void __launch_bounds__(128) k_edge(const float* __restrict__ bias,
                                              float* __restrict__ out_ext,
                                              int last) {
    __shared__ int   s_src[32];
    __shared__ float s_w[32][4];
    __shared__ float s_ed[4];

    int node = blockIdx.x;
    int t = threadIdx.x;
    int hd = t >> 5;
    int beg = g_off[node];
    int end = g_off[node + 1];

    if (t < 4) s_ed[t] = g_ed[node * HH + t];
    __syncthreads();

    float acc = 0.f;
    float wsum = 0.f;

    for (int base = beg; base < end; base += 32) {
        int m = min(32, end - base);
        if (t < m) {
            int s = g_csr[base + t];
            s_src[t] = s;
            float4 e = *(const float4*)(g_es + s * HH);
            float z0 = e.x + s_ed[0]; z0 = (z0 > 0.f) ? z0 : NEG_SLOPE * z0;
            float z1 = e.y + s_ed[1]; z1 = (z1 > 0.f) ? z1 : NEG_SLOPE * z1;
            float z2 = e.z + s_ed[2]; z2 = (z2 > 0.f) ? z2 : NEG_SLOPE * z2;
            float z3 = e.w + s_ed[3]; z3 = (z3 > 0.f) ? z3 : NEG_SLOPE * z3;
            s_w[t][0] = __expf(z0);
            s_w[t][1] = __expf(z1);
            s_w[t][2] = __expf(z2);
            s_w[t][3] = __expf(z3);
        }
        __syncthreads();
#pragma unroll 4
        for (int j = 0; j < m; j++) {
            float w = s_w[j][hd];
            int s = s_src[j];
            acc += w * __ldg(&g_h[(size_t)s * FF + t]);
            wsum += w;
        }
        __syncthreads();
    }

    float o = acc / wsum + bias[t];
    if (!last) o = (o > 0.f) ? o : (__expf(o) - 1.f);
    float* out = last ? out_ext : g_feat;
    out[(size_t)node * FF + t] = o;
}

// ----------------------------------------------------------------------------
// Launch. GEMM layer 0 is independent of the CSR build, so it is placed at
// launch index 3 (the slot ncu captures) to get its profile.
// ----------------------------------------------------------------------------
extern "C" void kernel_launch(void* const* d_in, const int* in_sizes, int n_in,
                              void* d_out, int out_size) {
    const float* x  = (const float*)d_in[0];
    const void*  ei = d_in[1];
    const float* W[3]  = {(const float*)d_in[2], (const float*)d_in[6],  (const float*)d_in[10]};
    const float* AS[3] = {(const float*)d_in[3], (const float*)d_in[7],  (const float*)d_in[11]};
    const float* AD[3] = {(const float*)d_in[4], (const float*)d_in[8],  (const float*)d_in[12]};
    const float* B[3]  = {(const float*)d_in[5], (const float*)d_in[9],  (const float*)d_in[13]};
    float* out = (float*)d_out;

    const int gemm_blocks = (NN + 63) / 64;

    k_detect<<<1, 32>>>((const int*)ei);                       // 0
    k_init_counts<<<(NN + 255) / 256, 256>>>();                // 1
    k_count<<<(EE + 255) / 256, 256>>>(ei);                    // 2
    k_gemm<<<gemm_blocks, 256>>>(x, W[0], AS[0], AD[0], 0);    // 3  <- profiled
    k_blocksum<<<SCAN_B, 1024>>>();                            // 4
    k_scan_top<<<1, 128>>>();                                  // 5
    k_scan_final<<<SCAN_B, 1024>>>();                          // 6
    k_scatter<<<(ET + 255) / 256, 256>>>(ei);                  // 7

    k_edge<<<NN, 128>>>(B[0], out, 0);
    for (int L = 1; L < 3; L++) {
        k_gemm<<<gemm_blocks, 256>>>(x, W[L], AS[L], AD[L], 1);
        k_edge<<<NN, 128>>>(B[L], out, L == 2 ? 1 : 0);
    }
}

// round 6
// speedup vs baseline: 1.0864x; 1.0864x over previous
#include <cuda_runtime.h>
#include <math.h>

// Problem constants
#define NN 100000
#define EE 1600000
#define ET (EE + NN)      // edges + self loops
#define FF 128            // feature dim everywhere (IN = H*C = 128)
#define HH 4
#define CC 32
#define NEG_SLOPE 0.2f
#define SCAN_B 98         // 98 * 1024 >= NN

// ----------------------------------------------------------------------------
// Scratch (device globals; no allocations allowed)
// ----------------------------------------------------------------------------
__device__ float g_h[(size_t)NN * FF];     // transformed features of current layer
__device__ float g_feat[(size_t)NN * FF];  // input features for layers 1,2
__device__ __align__(16) float g_es[NN * HH];
__device__ __align__(16) float g_ed[NN * HH];
__device__ int   g_off[NN + 1];
__device__ int   g_cur[NN];                // counts, then cursors
__device__ int   g_csr[ET];                // src node per CSR slot (grouped by dst)
__device__ int   g_bsum[SCAN_B];
__device__ int   g_is64;                   // 1 if edge_index is int64, 0 if int32

// ----------------------------------------------------------------------------
// Packed f32x2 helpers. Operands come straight from 64-bit shared loads so no
// ALU packing happens in the inner loop (R5 lesson: mov.b64 packs bound alu).
// ----------------------------------------------------------------------------
__device__ __forceinline__ void fma2(unsigned long long& d,
                                     unsigned long long a, unsigned long long b) {
    asm("fma.rn.f32x2 %0, %1, %2, %0;" : "+l"(d) : "l"(a), "l"(b));
}
__device__ __forceinline__ unsigned long long lds64(unsigned s_addr) {
    unsigned long long r;
    asm("ld.shared.b64 %0, [%1];" : "=l"(r) : "r"(s_addr));
    return r;
}
__device__ __forceinline__ float2 unpk(unsigned long long v) {
    float lo, hi;
    asm("mov.b64 {%0, %1}, %2;" : "=f"(lo), "=f"(hi) : "l"(v));
    return make_float2(lo, hi);
}

// ----------------------------------------------------------------------------
// Edge index dtype probe (JAX may give int32 or int64)
// ----------------------------------------------------------------------------
__global__ void k_detect(const int* __restrict__ ei32) {
    if (threadIdx.x == 0) {
        int all0 = 1;
        for (int j = 1; j < 256; j += 2)
            if (ei32[j] != 0) { all0 = 0; break; }
        g_is64 = all0;
    }
}

__device__ __forceinline__ int load_edge(const void* ei, size_t idx) {
    if (g_is64) return (int)((const long long*)ei)[idx];
    return ((const int*)ei)[idx];
}

// ----------------------------------------------------------------------------
// CSR build: counting sort by dst
// ----------------------------------------------------------------------------
__global__ void k_init_counts() {
    int n = blockIdx.x * blockDim.x + threadIdx.x;
    if (n < NN) g_cur[n] = 1;  // self loop
}

__global__ void k_count(const void* __restrict__ ei) {
    int i = blockIdx.x * blockDim.x + threadIdx.x;
    if (i < EE) {
        int d = load_edge(ei, (size_t)EE + i);
        atomicAdd(&g_cur[d], 1);
    }
}

__global__ void __launch_bounds__(1024) k_blocksum() {
    __shared__ int sh[32];
    int t = threadIdx.x;
    int g = blockIdx.x * 1024 + t;
    int c = (g < NN) ? g_cur[g] : 0;
#pragma unroll
    for (int o = 16; o; o >>= 1) c += __shfl_xor_sync(0xffffffffu, c, o);
    if ((t & 31) == 0) sh[t >> 5] = c;
    __syncthreads();
    if (t < 32) {
        int v = sh[t];
#pragma unroll
        for (int o = 16; o; o >>= 1) v += __shfl_xor_sync(0xffffffffu, v, o);
        if (t == 0) g_bsum[blockIdx.x] = v;
    }
}

__global__ void k_scan_top() {
    __shared__ int sh[SCAN_B];
    int t = threadIdx.x;
    if (t < SCAN_B) sh[t] = g_bsum[t];
    __syncthreads();
    if (t == 0) {
        int run = 0;
        for (int i = 0; i < SCAN_B; i++) { int c = sh[i]; sh[i] = run; run += c; }
    }
    __syncthreads();
    if (t < SCAN_B) g_bsum[t] = sh[t];
}

__global__ void __launch_bounds__(1024) k_scan_final() {
    __shared__ int sh[1024];
    int t = threadIdx.x;
    int g = blockIdx.x * 1024 + t;
    int c = (g < NN) ? g_cur[g] : 0;
    sh[t] = c;
    __syncthreads();
#pragma unroll
    for (int off = 1; off < 1024; off <<= 1) {
        int v = (t >= off) ? sh[t - off] : 0;
        __syncthreads();
        sh[t] += v;
        __syncthreads();
    }
    int excl = sh[t] - c + g_bsum[blockIdx.x];
    if (g < NN) {
        g_off[g] = excl;
        g_cur[g] = excl;
    }
    if (g == 0) g_off[NN] = ET;
}

__global__ void k_scatter(const void* __restrict__ ei) {
    int i = blockIdx.x * blockDim.x + threadIdx.x;
    if (i >= ET) return;
    int s, d;
    if (i < EE) {
        s = load_edge(ei, i);
        d = load_edge(ei, (size_t)EE + i);
    } else {
        s = d = i - EE;  // self loop
    }
    int p = atomicAdd(&g_cur[d], 1);
    g_csr[p] = s;
}

// ----------------------------------------------------------------------------
// GEMM: g_h = X[N,128] @ W[128,128], fused attention-coefficient epilogue.
// 64-row tile, k-tiled by 32; 256 threads; thread owns 8 rows x 4 cols.
// f32x2 over k-pairs; W pre-paired in smem as sWp[kp][col] = (W[2kp], W[2kp+1])
// so both fma2 operands are direct 64-bit shared loads (no inner-loop packs).
// ----------------------------------------------------------------------------
__global__ void __launch_bounds__(256, 2) k_gemm(const float* __restrict__ Xext,
                                                 const float* __restrict__ W,
                                                 const float* __restrict__ a_src,
                                                 const float* __restrict__ a_dst,
                                                 int use_gfeat) {
    const float* X = use_gfeat ? g_feat : Xext;
    __shared__ __align__(16) float sX[64 * 32];
    __shared__ __align__(16) float2 sWp[16 * 128];  // [kp][col]
    float4* sX4 = (float4*)sX;

    int tid = threadIdx.x;
    int row0 = blockIdx.x * 64;
    int cg = tid & 31;   // col group: cols 4*cg..4*cg+3 (also lane id)
    int rg = tid >> 5;   // row group (warp id): rows rg*8..rg*8+7

    unsigned sX_base, sWp_base;
    {
        unsigned long long gx = __cvta_generic_to_shared(sX);
        unsigned long long gw = __cvta_generic_to_shared(sWp);
        sX_base = (unsigned)gx;
        sWp_base = (unsigned)gw;
    }

    unsigned long long acc2[8][4];
#pragma unroll
    for (int i = 0; i < 8; i++)
#pragma unroll
        for (int c = 0; c < 4; c++) acc2[i][c] = 0ULL;

    for (int kt = 0; kt < 4; kt++) {
        int k0 = kt * 32;
        // X tile: 64 x 32 floats = 512 float4
#pragma unroll
        for (int j = 0; j < 2; j++) {
            int idx = tid + 256 * j;
            int r = idx >> 3, c4 = idx & 7;
            float4 v = make_float4(0.f, 0.f, 0.f, 0.f);
            int gr = row0 + r;
            if (gr < NN) v = *(const float4*)(X + (size_t)gr * FF + k0 + 4 * c4);
            sX4[idx] = v;
        }
        // W tile, pre-paired over k: thread handles k-pair rp (0..15) x 4 cols.
        // 512 (rp,c4) slots -> 2 iterations of 256 threads.
#pragma unroll
        for (int j = 0; j < 2; j++) {
            int idx = tid + 256 * j;
            int rp = idx >> 5, c4 = idx & 31;
            float4 w0 = *(const float4*)(W + (size_t)(k0 + 2 * rp) * FF + 4 * c4);
            float4 w1 = *(const float4*)(W + (size_t)(k0 + 2 * rp + 1) * FF + 4 * c4);
            float2* dst = sWp + rp * 128 + 4 * c4;
            dst[0] = make_float2(w0.x, w1.x);
            dst[1] = make_float2(w0.y, w1.y);
            dst[2] = make_float2(w0.z, w1.z);
            dst[3] = make_float2(w0.w, w1.w);
        }
        __syncthreads();

        unsigned xrow = sX_base + (rg * 8) * 32 * 4;  // byte addr of this warp's rows
        unsigned wcol = sWp_base + (4 * cg) * 8;      // byte addr of this thread's cols
#pragma unroll 4
        for (int kp = 0; kp < 16; kp++) {
            unsigned wk = wcol + kp * 128 * 8;
            unsigned long long b0 = lds64(wk);
            unsigned long long b1 = lds64(wk + 8);
            unsigned long long b2 = lds64(wk + 16);
            unsigned long long b3 = lds64(wk + 24);
#pragma unroll
            for (int i = 0; i < 8; i++) {
                unsigned long long a = lds64(xrow + i * 128 + kp * 8);
                fma2(acc2[i][0], a, b0);
                fma2(acc2[i][1], a, b1);
                fma2(acc2[i][2], a, b2);
                fma2(acc2[i][3], a, b3);
            }
        }
        __syncthreads();
    }

    float4 asv = *(const float4*)(a_src + 4 * cg);
    float4 adv = *(const float4*)(a_dst + 4 * cg);
    int head = cg >> 3;

#pragma unroll
    for (int i = 0; i < 8; i++) {
        float2 u0 = unpk(acc2[i][0]);
        float2 u1 = unpk(acc2[i][1]);
        float2 u2 = unpk(acc2[i][2]);
        float2 u3 = unpk(acc2[i][3]);
        float a0 = u0.x + u0.y;
        float a1 = u1.x + u1.y;
        float a2 = u2.x + u2.y;
        float a3 = u3.x + u3.y;

        int gr = row0 + rg * 8 + i;
        float vs = a0 * asv.x + a1 * asv.y + a2 * asv.z + a3 * asv.w;
        float vd = a0 * adv.x + a1 * adv.y + a2 * adv.z + a3 * adv.w;
#pragma unroll
        for (int o = 4; o; o >>= 1) {
            vs += __shfl_xor_sync(0xffffffffu, vs, o);
            vd += __shfl_xor_sync(0xffffffffu, vd, o);
        }
        if (gr < NN) {
            *(float4*)(g_h + (size_t)gr * FF + 4 * cg) = make_float4(a0, a1, a2, a3);
            if ((cg & 7) == 0) {
                g_es[gr * HH + head] = vs;
                g_ed[gr * HH + head] = vd;
            }
        }
    }
}

// ----------------------------------------------------------------------------
// Edge phase: per dst node, max-free softmax over incoming edges + aggregation.
// One 128-thread block per node; thread t owns channel t (head t>>5).
// ----------------------------------------------------------------------------
__global__ void __launch_bounds__(128) k_edge(const float* __restrict__ bias,
                                              float* __restrict__ out_ext,
                                              int last) {
    __shared__ int   s_src[32];
    __shared__ float s_w[32][4];
    __shared__ float s_ed[4];

    int node = blockIdx.x;
    int t = threadIdx.x;
    int hd = t >> 5;
    int beg = g_off[node];
    int end = g_off[node + 1];

    if (t < 4) s_ed[t] = g_ed[node * HH + t];
    __syncthreads();

    float acc = 0.f;
    float wsum = 0.f;

    for (int base = beg; base < end; base += 32) {
        int m = min(32, end - base);
        if (t < m) {
            int s = g_csr[base + t];
            s_src[t] = s;
            float4 e = *(const float4*)(g_es + s * HH);
            float z0 = e.x + s_ed[0]; z0 = (z0 > 0.f) ? z0 : NEG_SLOPE * z0;
            float z1 = e.y + s_ed[1]; z1 = (z1 > 0.f) ? z1 : NEG_SLOPE * z1;
            float z2 = e.z + s_ed[2]; z2 = (z2 > 0.f) ? z2 : NEG_SLOPE * z2;
            float z3 = e.w + s_ed[3]; z3 = (z3 > 0.f) ? z3 : NEG_SLOPE * z3;
            s_w[t][0] = __expf(z0);
            s_w[t][1] = __expf(z1);
            s_w[t][2] = __expf(z2);
            s_w[t][3] = __expf(z3);
        }
        __syncthreads();
#pragma unroll 4
        for (int j = 0; j < m; j++) {
            float w = s_w[j][hd];
            int s = s_src[j];
            acc += w * __ldg(&g_h[(size_t)s * FF + t]);
            wsum += w;
        }
        __syncthreads();
    }

    float o = acc / wsum + bias[t];
    if (!last) o = (o > 0.f) ? o : (__expf(o) - 1.f);
    float* out = last ? out_ext : g_feat;
    out[(size_t)node * FF + t] = o;
}

// ----------------------------------------------------------------------------
// Launch. GEMM layer 0 stays at launch index 3 so ncu profiles it.
// ----------------------------------------------------------------------------
extern "C" void kernel_launch(void* const* d_in, const int* in_sizes, int n_in,
                              void* d_out, int out_size) {
    const float* x  = (const float*)d_in[0];
    const void*  ei = d_in[1];
    const float* W[3]  = {(const float*)d_in[2], (const float*)d_in[6],  (const float*)d_in[10]};
    const float* AS[3] = {(const float*)d_in[3], (const float*)d_in[7],  (const float*)d_in[11]};
    const float* AD[3] = {(const float*)d_in[4], (const float*)d_in[8],  (const float*)d_in[12]};
    const float* B[3]  = {(const float*)d_in[5], (const float*)d_in[9],  (const float*)d_in[13]};
    float* out = (float*)d_out;

    const int gemm_blocks = (NN + 63) / 64;

    k_detect<<<1, 32>>>((const int*)ei);                       // 0
    k_init_counts<<<(NN + 255) / 256, 256>>>();                // 1
    k_count<<<(EE + 255) / 256, 256>>>(ei);                    // 2
    k_gemm<<<gemm_blocks, 256>>>(x, W[0], AS[0], AD[0], 0);    // 3  <- profiled
    k_blocksum<<<SCAN_B, 1024>>>();                            // 4
    k_scan_top<<<1, 128>>>();                                  // 5
    k_scan_final<<<SCAN_B, 1024>>>();                          // 6
    k_scatter<<<(ET + 255) / 256, 256>>>(ei);                  // 7

    k_edge<<<NN, 128>>>(B[0], out, 0);
    for (int L = 1; L < 3; L++) {
        k_gemm<<<gemm_blocks, 256>>>(x, W[L], AS[L], AD[L], 1);
        k_edge<<<NN, 128>>>(B[L], out, L == 2 ? 1 : 0);
    }
}

// round 7
// speedup vs baseline: 1.6565x; 1.5248x over previous
#include <cuda_runtime.h>
#include <math.h>

// Problem constants
#define NN 100000
#define EE 1600000
#define ET (EE + NN)      // edges + self loops
#define FF 128            // feature dim everywhere (IN = H*C = 128)
#define HH 4
#define CC 32
#define NEG_SLOPE 0.2f
#define SCAN_B 98         // 98 * 1024 >= NN

// ----------------------------------------------------------------------------
// Scratch (device globals; no allocations allowed)
// ----------------------------------------------------------------------------
__device__ float g_h[(size_t)NN * FF];     // transformed features of current layer
__device__ float g_feat[(size_t)NN * FF];  // input features for layers 1,2
__device__ __align__(16) float g_es[NN * HH];
__device__ __align__(16) float g_ed[NN * HH];
__device__ int   g_off[NN + 1];
__device__ int   g_cur[NN];                // counts, then cursors
__device__ int   g_csr[ET];                // src node per CSR slot (grouped by dst)
__device__ int   g_bsum[SCAN_B];
__device__ int   g_is64;                   // 1 if edge_index is int64, 0 if int32

// ----------------------------------------------------------------------------
// Edge index dtype probe (JAX may give int32 or int64)
// ----------------------------------------------------------------------------
__global__ void k_detect(const int* __restrict__ ei32) {
    if (threadIdx.x == 0) {
        int all0 = 1;
        for (int j = 1; j < 256; j += 2)
            if (ei32[j] != 0) { all0 = 0; break; }
        g_is64 = all0;
    }
}

__device__ __forceinline__ int load_edge(const void* ei, size_t idx) {
    if (g_is64) return (int)((const long long*)ei)[idx];
    return ((const int*)ei)[idx];
}

// ----------------------------------------------------------------------------
// CSR build: counting sort by dst
// ----------------------------------------------------------------------------
__global__ void k_init_counts() {
    int n = blockIdx.x * blockDim.x + threadIdx.x;
    if (n < NN) g_cur[n] = 1;  // self loop
}

__global__ void k_count(const void* __restrict__ ei) {
    int i = blockIdx.x * blockDim.x + threadIdx.x;
    if (i < EE) {
        int d = load_edge(ei, (size_t)EE + i);
        atomicAdd(&g_cur[d], 1);
    }
}

__global__ void __launch_bounds__(1024) k_blocksum() {
    __shared__ int sh[32];
    int t = threadIdx.x;
    int g = blockIdx.x * 1024 + t;
    int c = (g < NN) ? g_cur[g] : 0;
#pragma unroll
    for (int o = 16; o; o >>= 1) c += __shfl_xor_sync(0xffffffffu, c, o);
    if ((t & 31) == 0) sh[t >> 5] = c;
    __syncthreads();
    if (t < 32) {
        int v = sh[t];
#pragma unroll
        for (int o = 16; o; o >>= 1) v += __shfl_xor_sync(0xffffffffu, v, o);
        if (t == 0) g_bsum[blockIdx.x] = v;
    }
}

__global__ void k_scan_top() {
    __shared__ int sh[SCAN_B];
    int t = threadIdx.x;
    if (t < SCAN_B) sh[t] = g_bsum[t];
    __syncthreads();
    if (t == 0) {
        int run = 0;
        for (int i = 0; i < SCAN_B; i++) { int c = sh[i]; sh[i] = run; run += c; }
    }
    __syncthreads();
    if (t < SCAN_B) g_bsum[t] = sh[t];
}

__global__ void __launch_bounds__(1024) k_scan_final() {
    __shared__ int sh[1024];
    int t = threadIdx.x;
    int g = blockIdx.x * 1024 + t;
    int c = (g < NN) ? g_cur[g] : 0;
    sh[t] = c;
    __syncthreads();
#pragma unroll
    for (int off = 1; off < 1024; off <<= 1) {
        int v = (t >= off) ? sh[t - off] : 0;
        __syncthreads();
        sh[t] += v;
        __syncthreads();
    }
    int excl = sh[t] - c + g_bsum[blockIdx.x];
    if (g < NN) {
        g_off[g] = excl;
        g_cur[g] = excl;
    }
    if (g == 0) g_off[NN] = ET;
}

__global__ void k_scatter(const void* __restrict__ ei) {
    int i = blockIdx.x * blockDim.x + threadIdx.x;
    if (i >= ET) return;
    int s, d;
    if (i < EE) {
        s = load_edge(ei, i);
        d = load_edge(ei, (size_t)EE + i);
    } else {
        s = d = i - EE;  // self loop
    }
    int p = atomicAdd(&g_cur[d], 1);
    g_csr[p] = s;
}

// ----------------------------------------------------------------------------
// GEMM (R4 scalar version — measured fastest): g_h = X @ W, fused attention
// epilogue. 64-row tile, k-tiled by 32; 256 threads; thread = 8 rows x 4 cols.
// ----------------------------------------------------------------------------
__global__ void __launch_bounds__(256) k_gemm(const float* __restrict__ Xext,
                                              const float* __restrict__ W,
                                              const float* __restrict__ a_src,
                                              const float* __restrict__ a_dst,
                                              int use_gfeat) {
    const float* X = use_gfeat ? g_feat : Xext;
    __shared__ float sX[64 * 32];
    __shared__ float sW[32 * 128];
    float4* sX4 = (float4*)sX;
    float4* sW4 = (float4*)sW;

    int tid = threadIdx.x;
    int row0 = blockIdx.x * 64;
    int cg = tid & 31;   // col group: cols 4*cg..4*cg+3 (also lane id)
    int rg = tid >> 5;   // row group (warp id): rows rg*8..rg*8+7

    float acc[8][4] = {};

    for (int kt = 0; kt < 4; kt++) {
        int k0 = kt * 32;
#pragma unroll
        for (int j = 0; j < 2; j++) {
            int idx = tid + 256 * j;
            int r = idx >> 3, c4 = idx & 7;
            float4 v = make_float4(0.f, 0.f, 0.f, 0.f);
            int gr = row0 + r;
            if (gr < NN) v = *(const float4*)(X + (size_t)gr * FF + k0 + 4 * c4);
            sX4[idx] = v;
        }
#pragma unroll
        for (int j = 0; j < 4; j++) {
            int idx = tid + 256 * j;
            int r = idx >> 5, c4 = idx & 31;
            sW4[idx] = *(const float4*)(W + (size_t)(k0 + r) * FF + 4 * c4);
        }
        __syncthreads();
#pragma unroll
        for (int kk = 0; kk < 32; kk++) {
            float4 w = sW4[kk * 32 + cg];
#pragma unroll
            for (int i = 0; i < 8; i++) {
                float xv = sX[(rg * 8 + i) * 32 + kk];
                acc[i][0] += xv * w.x;
                acc[i][1] += xv * w.y;
                acc[i][2] += xv * w.z;
                acc[i][3] += xv * w.w;
            }
        }
        __syncthreads();
    }

    float4 asv = *(const float4*)(a_src + 4 * cg);
    float4 adv = *(const float4*)(a_dst + 4 * cg);
    int head = cg >> 3;

#pragma unroll
    for (int i = 0; i < 8; i++) {
        int gr = row0 + rg * 8 + i;
        float vs = acc[i][0] * asv.x + acc[i][1] * asv.y + acc[i][2] * asv.z + acc[i][3] * asv.w;
        float vd = acc[i][0] * adv.x + acc[i][1] * adv.y + acc[i][2] * adv.z + acc[i][3] * adv.w;
#pragma unroll
        for (int o = 4; o; o >>= 1) {
            vs += __shfl_xor_sync(0xffffffffu, vs, o);
            vd += __shfl_xor_sync(0xffffffffu, vd, o);
        }
        if (gr < NN) {
            *(float4*)(g_h + (size_t)gr * FF + 4 * cg) =
                make_float4(acc[i][0], acc[i][1], acc[i][2], acc[i][3]);
            if ((cg & 7) == 0) {
                g_es[gr * HH + head] = vs;
                g_ed[gr * HH + head] = vd;
            }
        }
    }
}

// ----------------------------------------------------------------------------
// Edge phase: WARP per dst node. Lane l owns channels 4l..4l+3 (head l>>3).
// Per edge: 1 LDG.128 gather + 2 LDS + 4 FFMA (vs 4 warps x scalar before).
// wsum needs no reduction: every lane accumulates all 4-head weights' own-head
// value identically across j.
// ----------------------------------------------------------------------------
__global__ void __launch_bounds__(128) k_edge(const float* __restrict__ bias,
                                              float* __restrict__ out_ext,
                                              int last) {
    __shared__ int   s_src[4][32];
    __shared__ float s_w[4][32][4];

    int wid = threadIdx.x >> 5;
    int lane = threadIdx.x & 31;
    int node = blockIdx.x * 4 + wid;   // NN = 4 * 25000 exactly
    int hd = lane >> 3;

    int beg = g_off[node];
    int end = g_off[node + 1];
    float4 ed4 = *(const float4*)(g_ed + node * HH);

    float4 acc = make_float4(0.f, 0.f, 0.f, 0.f);
    float wsum = 0.f;

    for (int base = beg; base < end; base += 32) {
        int m = min(32, end - base);
        if (lane < m) {
            int s = g_csr[base + lane];
            s_src[wid][lane] = s;
            float4 e = *(const float4*)(g_es + s * HH);
            float z0 = e.x + ed4.x; z0 = (z0 > 0.f) ? z0 : NEG_SLOPE * z0;
            float z1 = e.y + ed4.y; z1 = (z1 > 0.f) ? z1 : NEG_SLOPE * z1;
            float z2 = e.z + ed4.z; z2 = (z2 > 0.f) ? z2 : NEG_SLOPE * z2;
            float z3 = e.w + ed4.w; z3 = (z3 > 0.f) ? z3 : NEG_SLOPE * z3;
            s_w[wid][lane][0] = __expf(z0);
            s_w[wid][lane][1] = __expf(z1);
            s_w[wid][lane][2] = __expf(z2);
            s_w[wid][lane][3] = __expf(z3);
        }
        __syncwarp();
#pragma unroll 4
        for (int j = 0; j < m; j++) {
            float w = s_w[wid][j][hd];
            int s = s_src[wid][j];
            float4 f = *(const float4*)(g_h + (size_t)s * FF + 4 * lane);
            acc.x += w * f.x;
            acc.y += w * f.y;
            acc.z += w * f.z;
            acc.w += w * f.w;
            wsum += w;
        }
        __syncwarp();
    }

    float inv = 1.f / wsum;
    float4 b4 = *(const float4*)(bias + 4 * lane);
    float4 o;
    o.x = acc.x * inv + b4.x;
    o.y = acc.y * inv + b4.y;
    o.z = acc.z * inv + b4.z;
    o.w = acc.w * inv + b4.w;
    if (!last) {
        o.x = (o.x > 0.f) ? o.x : (__expf(o.x) - 1.f);
        o.y = (o.y > 0.f) ? o.y : (__expf(o.y) - 1.f);
        o.z = (o.z > 0.f) ? o.z : (__expf(o.z) - 1.f);
        o.w = (o.w > 0.f) ? o.w : (__expf(o.w) - 1.f);
    }
    float* out = last ? out_ext : g_feat;
    *(float4*)(out + (size_t)node * FF + 4 * lane) = o;
}

// ----------------------------------------------------------------------------
// Launch. GEMM layer 0 stays at launch index 3 so ncu profiles it (first
// direct measurement of the scalar GEMM).
// ----------------------------------------------------------------------------
extern "C" void kernel_launch(void* const* d_in, const int* in_sizes, int n_in,
                              void* d_out, int out_size) {
    const float* x  = (const float*)d_in[0];
    const void*  ei = d_in[1];
    const float* W[3]  = {(const float*)d_in[2], (const float*)d_in[6],  (const float*)d_in[10]};
    const float* AS[3] = {(const float*)d_in[3], (const float*)d_in[7],  (const float*)d_in[11]};
    const float* AD[3] = {(const float*)d_in[4], (const float*)d_in[8],  (const float*)d_in[12]};
    const float* B[3]  = {(const float*)d_in[5], (const float*)d_in[9],  (const float*)d_in[13]};
    float* out = (float*)d_out;

    const int gemm_blocks = (NN + 63) / 64;

    k_detect<<<1, 32>>>((const int*)ei);                       // 0
    k_init_counts<<<(NN + 255) / 256, 256>>>();                // 1
    k_count<<<(EE + 255) / 256, 256>>>(ei);                    // 2
    k_gemm<<<gemm_blocks, 256>>>(x, W[0], AS[0], AD[0], 0);    // 3  <- profiled
    k_blocksum<<<SCAN_B, 1024>>>();                            // 4
    k_scan_top<<<1, 128>>>();                                  // 5
    k_scan_final<<<SCAN_B, 1024>>>();                          // 6
    k_scatter<<<(ET + 255) / 256, 256>>>(ei);                  // 7

    k_edge<<<NN / 4, 128>>>(B[0], out, 0);
    for (int L = 1; L < 3; L++) {
        k_gemm<<<gemm_blocks, 256>>>(x, W[L], AS[L], AD[L], 1);
        k_edge<<<NN / 4, 128>>>(B[L], out, L == 2 ? 1 : 0);
    }
}

// round 8
// speedup vs baseline: 1.6625x; 1.0036x over previous
#include <cuda_runtime.h>
#include <math.h>

// Problem constants
#define NN 100000
#define EE 1600000
#define ET (EE + NN)      // edges + self loops
#define FF 128            // feature dim everywhere (IN = H*C = 128)
#define HH 4
#define CC 32
#define NEG_SLOPE 0.2f
#define SCAN_B 98         // 98 * 1024 >= NN

// ----------------------------------------------------------------------------
// Scratch (device globals; no allocations allowed)
// ----------------------------------------------------------------------------
__device__ float g_h[(size_t)NN * FF];     // transformed features of current layer
__device__ float g_feat[(size_t)NN * FF];  // input features for layers 1,2
__device__ __align__(16) float g_es[NN * HH];
__device__ __align__(16) float g_ed[NN * HH];
__device__ int   g_off[NN + 1];
__device__ int   g_cur[NN];                // counts, then cursors
__device__ int   g_csr[ET];                // src node per CSR slot (grouped by dst)
__device__ int   g_bsum[SCAN_B];
__device__ int   g_is64;                   // 1 if edge_index is int64, 0 if int32

// ----------------------------------------------------------------------------
// Edge index dtype probe (JAX may give int32 or int64)
// ----------------------------------------------------------------------------
__global__ void k_detect(const int* __restrict__ ei32) {
    if (threadIdx.x == 0) {
        int all0 = 1;
        for (int j = 1; j < 256; j += 2)
            if (ei32[j] != 0) { all0 = 0; break; }
        g_is64 = all0;
    }
}

__device__ __forceinline__ int load_edge(const void* ei, size_t idx) {
    if (g_is64) return (int)((const long long*)ei)[idx];
    return ((const int*)ei)[idx];
}

// ----------------------------------------------------------------------------
// CSR build: counting sort by dst
// ----------------------------------------------------------------------------
__global__ void k_init_counts() {
    int n = blockIdx.x * blockDim.x + threadIdx.x;
    if (n < NN) g_cur[n] = 1;  // self loop
}

__global__ void k_count(const void* __restrict__ ei) {
    int i = blockIdx.x * blockDim.x + threadIdx.x;
    if (i < EE) {
        int d = load_edge(ei, (size_t)EE + i);
        atomicAdd(&g_cur[d], 1);
    }
}

__global__ void __launch_bounds__(1024) k_blocksum() {
    __shared__ int sh[32];
    int t = threadIdx.x;
    int g = blockIdx.x * 1024 + t;
    int c = (g < NN) ? g_cur[g] : 0;
#pragma unroll
    for (int o = 16; o; o >>= 1) c += __shfl_xor_sync(0xffffffffu, c, o);
    if ((t & 31) == 0) sh[t >> 5] = c;
    __syncthreads();
    if (t < 32) {
        int v = sh[t];
#pragma unroll
        for (int o = 16; o; o >>= 1) v += __shfl_xor_sync(0xffffffffu, v, o);
        if (t == 0) g_bsum[blockIdx.x] = v;
    }
}

__global__ void k_scan_top() {
    __shared__ int sh[SCAN_B];
    int t = threadIdx.x;
    if (t < SCAN_B) sh[t] = g_bsum[t];
    __syncthreads();
    if (t == 0) {
        int run = 0;
        for (int i = 0; i < SCAN_B; i++) { int c = sh[i]; sh[i] = run; run += c; }
    }
    __syncthreads();
    if (t < SCAN_B) g_bsum[t] = sh[t];
}

__global__ void __launch_bounds__(1024) k_scan_final() {
    __shared__ int sh[1024];
    int t = threadIdx.x;
    int g = blockIdx.x * 1024 + t;
    int c = (g < NN) ? g_cur[g] : 0;
    sh[t] = c;
    __syncthreads();
#pragma unroll
    for (int off = 1; off < 1024; off <<= 1) {
        int v = (t >= off) ? sh[t - off] : 0;
        __syncthreads();
        sh[t] += v;
        __syncthreads();
    }
    int excl = sh[t] - c + g_bsum[blockIdx.x];
    if (g < NN) {
        g_off[g] = excl;
        g_cur[g] = excl;
    }
    if (g == 0) g_off[NN] = ET;
}

__global__ void k_scatter(const void* __restrict__ ei) {
    int i = blockIdx.x * blockDim.x + threadIdx.x;
    if (i >= ET) return;
    int s, d;
    if (i < EE) {
        s = load_edge(ei, i);
        d = load_edge(ei, (size_t)EE + i);
    } else {
        s = d = i - EE;  // self loop
    }
    int p = atomicAdd(&g_cur[d], 1);
    g_csr[p] = s;
}

// ----------------------------------------------------------------------------
// GEMM (R4 scalar version — measured fastest): g_h = X @ W, fused attention
// epilogue. 64-row tile, k-tiled by 32; 256 threads; thread = 8 rows x 4 cols.
// ----------------------------------------------------------------------------
__global__ void __launch_bounds__(256) k_gemm(const float* __restrict__ Xext,
                                              const float* __restrict__ W,
                                              const float* __restrict__ a_src,
                                              const float* __restrict__ a_dst,
                                              int use_gfeat) {
    const float* X = use_gfeat ? g_feat : Xext;
    __shared__ float sX[64 * 32];
    __shared__ float sW[32 * 128];
    float4* sX4 = (float4*)sX;
    float4* sW4 = (float4*)sW;

    int tid = threadIdx.x;
    int row0 = blockIdx.x * 64;
    int cg = tid & 31;   // col group: cols 4*cg..4*cg+3 (also lane id)
    int rg = tid >> 5;   // row group (warp id): rows rg*8..rg*8+7

    float acc[8][4] = {};

    for (int kt = 0; kt < 4; kt++) {
        int k0 = kt * 32;
#pragma unroll
        for (int j = 0; j < 2; j++) {
            int idx = tid + 256 * j;
            int r = idx >> 3, c4 = idx & 7;
            float4 v = make_float4(0.f, 0.f, 0.f, 0.f);
            int gr = row0 + r;
            if (gr < NN) v = *(const float4*)(X + (size_t)gr * FF + k0 + 4 * c4);
            sX4[idx] = v;
        }
#pragma unroll
        for (int j = 0; j < 4; j++) {
            int idx = tid + 256 * j;
            int r = idx >> 5, c4 = idx & 31;
            sW4[idx] = *(const float4*)(W + (size_t)(k0 + r) * FF + 4 * c4);
        }
        __syncthreads();
#pragma unroll
        for (int kk = 0; kk < 32; kk++) {
            float4 w = sW4[kk * 32 + cg];
#pragma unroll
            for (int i = 0; i < 8; i++) {
                float xv = sX[(rg * 8 + i) * 32 + kk];
                acc[i][0] += xv * w.x;
                acc[i][1] += xv * w.y;
                acc[i][2] += xv * w.z;
                acc[i][3] += xv * w.w;
            }
        }
        __syncthreads();
    }

    float4 asv = *(const float4*)(a_src + 4 * cg);
    float4 adv = *(const float4*)(a_dst + 4 * cg);
    int head = cg >> 3;

#pragma unroll
    for (int i = 0; i < 8; i++) {
        int gr = row0 + rg * 8 + i;
        float vs = acc[i][0] * asv.x + acc[i][1] * asv.y + acc[i][2] * asv.z + acc[i][3] * asv.w;
        float vd = acc[i][0] * adv.x + acc[i][1] * adv.y + acc[i][2] * adv.z + acc[i][3] * adv.w;
#pragma unroll
        for (int o = 4; o; o >>= 1) {
            vs += __shfl_xor_sync(0xffffffffu, vs, o);
            vd += __shfl_xor_sync(0xffffffffu, vd, o);
        }
        if (gr < NN) {
            *(float4*)(g_h + (size_t)gr * FF + 4 * cg) =
                make_float4(acc[i][0], acc[i][1], acc[i][2], acc[i][3]);
            if ((cg & 7) == 0) {
                g_es[gr * HH + head] = vs;
                g_ed[gr * HH + head] = vd;
            }
        }
    }
}

// ----------------------------------------------------------------------------
// Edge phase: WARP per dst node. Lane l owns channels 4l..4l+3 (head l>>3).
// Per edge: 1 LDG.128 gather + 2 LDS + 4 FFMA (vs 4 warps x scalar before).
// wsum needs no reduction: every lane accumulates all 4-head weights' own-head
// value identically across j.
// ----------------------------------------------------------------------------
__global__ void __launch_bounds__(128) k_edge(const float* __restrict__ bias,
                                              float* __restrict__ out_ext,
                                              int last) {
    __shared__ int   s_src[4][32];
    __shared__ float s_w[4][32][4];

    int wid = threadIdx.x >> 5;
    int lane = threadIdx.x & 31;
    int node = blockIdx.x * 4 + wid;   // NN = 4 * 25000 exactly
    int hd = lane >> 3;

    int beg = g_off[node];
    int end = g_off[node + 1];
    float4 ed4 = *(const float4*)(g_ed + node * HH);

    float4 acc = make_float4(0.f, 0.f, 0.f, 0.f);
    float wsum = 0.f;

    for (int base = beg; base < end; base += 32) {
        int m = min(32, end - base);
        if (lane < m) {
            int s = g_csr[base + lane];
            s_src[wid][lane] = s;
            float4 e = *(const float4*)(g_es + s * HH);
            float z0 = e.x + ed4.x; z0 = (z0 > 0.f) ? z0 : NEG_SLOPE * z0;
            float z1 = e.y + ed4.y; z1 = (z1 > 0.f) ? z1 : NEG_SLOPE * z1;
            float z2 = e.z + ed4.z; z2 = (z2 > 0.f) ? z2 : NEG_SLOPE * z2;
            float z3 = e.w + ed4.w; z3 = (z3 > 0.f) ? z3 : NEG_SLOPE * z3;
            s_w[wid][lane][0] = __expf(z0);
            s_w[wid][lane][1] = __expf(z1);
            s_w[wid][lane][2] = __expf(z2);
            s_w[wid][lane][3] = __expf(z3);
        }
        __syncwarp();
#pragma unroll 4
        for (int j = 0; j < m; j++) {
            float w = s_w[wid][j][hd];
            int s = s_src[wid][j];
            float4 f = *(const float4*)(g_h + (size_t)s * FF + 4 * lane);
            acc.x += w * f.x;
            acc.y += w * f.y;
            acc.z += w * f.z;
            acc.w += w * f.w;
            wsum += w;
        }
        __syncwarp();
    }

    float inv = 1.f / wsum;
    float4 b4 = *(const float4*)(bias + 4 * lane);
    float4 o;
    o.x = acc.x * inv + b4.x;
    o.y = acc.y * inv + b4.y;
    o.z = acc.z * inv + b4.z;
    o.w = acc.w * inv + b4.w;
    if (!last) {
        o.x = (o.x > 0.f) ? o.x : (__expf(o.x) - 1.f);
        o.y = (o.y > 0.f) ? o.y : (__expf(o.y) - 1.f);
        o.z = (o.z > 0.f) ? o.z : (__expf(o.z) - 1.f);
        o.w = (o.w > 0.f) ? o.w : (__expf(o.w) - 1.f);
    }
    float* out = last ? out_ext : g_feat;
    *(float4*)(out + (size_t)node * FF + 4 * lane) = o;
}

// ----------------------------------------------------------------------------
// Launch. GEMM layer 0 stays at launch index 3 so ncu profiles it (first
// direct measurement of the scalar GEMM).
// ----------------------------------------------------------------------------
extern "C" void kernel_launch(void* const* d_in, const int* in_sizes, int n_in,
                              void* d_out, int out_size) {
    const float* x  = (const float*)d_in[0];
    const void*  ei = d_in[1];
    const float* W[3]  = {(const float*)d_in[2], (const float*)d_in[6],  (const float*)d_in[10]};
    const float* AS[3] = {(const float*)d_in[3], (const float*)d_in[7],  (const float*)d_in[11]};
    const float* AD[3] = {(const float*)d_in[4], (const float*)d_in[8],  (const float*)d_in[12]};
    const float* B[3]  = {(const float*)d_in[5], (const float*)d_in[9],  (const float*)d_in[13]};
    float* out = (float*)d_out;

    const int gemm_blocks = (NN + 63) / 64;

    k_detect<<<1, 32>>>((const int*)ei);                       // 0
    k_init_counts<<<(NN + 255) / 256, 256>>>();                // 1
    k_count<<<(EE + 255) / 256, 256>>>(ei);                    // 2
    k_gemm<<<gemm_blocks, 256>>>(x, W[0], AS[0], AD[0], 0);    // 3  <- profiled
    k_blocksum<<<SCAN_B, 1024>>>();                            // 4
    k_scan_top<<<1, 128>>>();                                  // 5
    k_scan_final<<<SCAN_B, 1024>>>();                          // 6
    k_scatter<<<(ET + 255) / 256, 256>>>(ei);                  // 7

    k_edge<<<NN / 4, 128>>>(B[0], out, 0);
    for (int L = 1; L < 3; L++) {
        k_gemm<<<gemm_blocks, 256>>>(x, W[L], AS[L], AD[L], 1);
        k_edge<<<NN / 4, 128>>>(B[L], out, L == 2 ? 1 : 0);
    }
}